// round 2
// baseline (speedup 1.0000x reference)
#include <cuda_runtime.h>

#define SEQ 192
#define NH 8

// ---------------- scratch ----------------
__device__ float g_xn[SEQ * 512];
__device__ float g_proj[SEQ * 2560];
__device__ float g_bsum[SEQ * 64];
__device__ float g_wkr[4096 * 512];
__device__ float g_step1[SEQ * 4096];
__device__ float g_step2[SEQ * SEQ * 64];         // [r][q][i]
__device__ float g_dT[NH * 64 * SEQ];             // [n][h][p]
__device__ float g_F[NH * SEQ * SEQ * 64];        // [n][r][p][g]
__device__ float g_Z[NH * SEQ];
__device__ float g_U[NH * SEQ * 4096];            // [n][r][h*64+g]
__device__ float g_zbuf[SEQ * 512];

typedef unsigned long long u64t;

__device__ __forceinline__ u64t pk2(float lo, float hi) {
    u64t d; asm("mov.b64 %0, {%1, %2};" : "=l"(d) : "f"(lo), "f"(hi)); return d;
}
__device__ __forceinline__ float2 upk2(u64t d) {
    float2 r; asm("mov.b64 {%0, %1}, %2;" : "=f"(r.x), "=f"(r.y) : "l"(d)); return r;
}
__device__ __forceinline__ u64t ffma2(u64t a, u64t b, u64t c) {
    u64t d; asm("fma.rn.f32x2 %0, %1, %2, %3;" : "=l"(d) : "l"(a), "l"(b), "l"(c)); return d;
}

// FMA-only exp (avoid MUFU bottleneck)
__device__ __forceinline__ float fexp(float x) {
    float t = fmaf(x, 1.4426950408889634f, 12582912.0f);
    float kf = t - 12582912.0f;
    int ki = (int)kf;
    float r = fmaf(kf, -0.69314718055994531f, x);
    float p = 1.38888889e-3f;
    p = fmaf(p, r, 8.33333333e-3f);
    p = fmaf(p, r, 4.16666667e-2f);
    p = fmaf(p, r, 1.66666667e-1f);
    p = fmaf(p, r, 0.5f);
    p = fmaf(p, r, 1.0f);
    p = fmaf(p, r, 1.0f);
    return p * __int_as_float((ki + 127) << 23);
}

// ---------------- LayerNorm ----------------
__global__ __launch_bounds__(256) void ln_kernel(const float* __restrict__ x,
                                                 const float* __restrict__ w,
                                                 const float* __restrict__ b,
                                                 float* __restrict__ xn) {
    __shared__ float rs[256], rq[256];
    int row = blockIdx.x, tid = threadIdx.x;
    float v0 = x[row * 512 + tid], v1 = x[row * 512 + 256 + tid];
    rs[tid] = v0 + v1;
    rq[tid] = v0 * v0 + v1 * v1;
    __syncthreads();
    for (int s = 128; s >= 32; s >>= 1) {
        if (tid < s) { rs[tid] += rs[tid + s]; rq[tid] += rq[tid + s]; }
        __syncthreads();
    }
    if (tid < 32) {
        float a = rs[tid], q = rq[tid];
        for (int o = 16; o; o >>= 1) {
            a += __shfl_down_sync(~0u, a, o);
            q += __shfl_down_sync(~0u, q, o);
        }
        if (!tid) { rs[0] = a; rq[0] = q; }
    }
    __syncthreads();
    float mu = rs[0] * (1.f / 512.f);
    float var = rq[0] * (1.f / 512.f) - mu * mu;
    float is = rsqrtf(var + 1e-5f);
    xn[row * 512 + tid]       = (v0 - mu) * is * w[tid]       + b[tid];
    xn[row * 512 + 256 + tid] = (v1 - mu) * is * w[256 + tid] + b[256 + tid];
}

// ---------------- generic GEMM: C[m,nn] = sum_k A[m,k]*B[nn,k] -----------
// 64x64 tile, BK=16, 128 threads, thread tile 8m x 4n, f32x2 packed on m.
// blockIdx.z = ((b2*nb1)+b1)*kSplits + kz
__global__ __launch_bounds__(128) void gemm_kernel(
    const float* __restrict__ A, int lda, long sA1, long sA2,
    const float* __restrict__ B, int ldbn, int ldbk, long sB1, long sB2,
    float* __restrict__ C, int ldc, long sC1, long sC2,
    const float* __restrict__ bias,
    int K, int nb1, int kSplits, int doAtomic)
{
    __shared__ float Ast[16][68];
    __shared__ float Bst[16][68];
    int z = blockIdx.z;
    int kz = z % kSplits;
    int t = z / kSplits;
    int b1 = t % nb1, b2 = t / nb1;
    A += b1 * sA1 + b2 * sA2;
    B += b1 * sB1 + b2 * sB2;
    C += b1 * sC1 + b2 * sC2;
    const int kPer = K / kSplits;
    const int k0 = kz * kPer, k1 = k0 + kPer;
    const int m0 = blockIdx.y * 64;
    const int n0 = blockIdx.x * 64;
    const int tid = threadIdx.x;
    const int tn0 = (tid & 15) * 4;
    const int tm0 = (tid >> 4) * 8;

    u64t acc[4][4];
#pragma unroll
    for (int i = 0; i < 4; i++)
#pragma unroll
        for (int j = 0; j < 4; j++) acc[i][j] = 0ULL;

    for (int kk = k0; kk < k1; kk += 16) {
#pragma unroll
        for (int j = 0; j < 2; j++) {
            int idx = tid + j * 128;
            int m = idx >> 2, kq = (idx & 3) * 4;
            float4 v = *(const float4*)(A + (long)(m0 + m) * lda + kk + kq);
            Ast[kq + 0][m] = v.x; Ast[kq + 1][m] = v.y;
            Ast[kq + 2][m] = v.z; Ast[kq + 3][m] = v.w;
        }
        if (ldbk == 1) {
#pragma unroll
            for (int j = 0; j < 2; j++) {
                int idx = tid + j * 128;
                int nn = idx >> 2, kq = (idx & 3) * 4;
                float4 v = *(const float4*)(B + (long)(n0 + nn) * ldbn + kk + kq);
                Bst[kq + 0][nn] = v.x; Bst[kq + 1][nn] = v.y;
                Bst[kq + 2][nn] = v.z; Bst[kq + 3][nn] = v.w;
            }
        } else {
#pragma unroll
            for (int j = 0; j < 8; j++) {
                int idx = tid + j * 128;
                int nn = idx & 63, k = idx >> 6;
                Bst[k][nn] = B[(long)(kk + k) * ldbk + (long)(n0 + nn) * ldbn];
            }
        }
        __syncthreads();
#pragma unroll
        for (int k = 0; k < 16; k++) {
            ulonglong2 a01 = *(const ulonglong2*)&Ast[k][tm0];
            ulonglong2 a23 = *(const ulonglong2*)&Ast[k][tm0 + 4];
            float4 bv = *(const float4*)&Bst[k][tn0];
            u64t b0 = pk2(bv.x, bv.x), b1p = pk2(bv.y, bv.y);
            u64t b2p = pk2(bv.z, bv.z), b3p = pk2(bv.w, bv.w);
            acc[0][0] = ffma2(a01.x, b0, acc[0][0]);
            acc[0][1] = ffma2(a01.x, b1p, acc[0][1]);
            acc[0][2] = ffma2(a01.x, b2p, acc[0][2]);
            acc[0][3] = ffma2(a01.x, b3p, acc[0][3]);
            acc[1][0] = ffma2(a01.y, b0, acc[1][0]);
            acc[1][1] = ffma2(a01.y, b1p, acc[1][1]);
            acc[1][2] = ffma2(a01.y, b2p, acc[1][2]);
            acc[1][3] = ffma2(a01.y, b3p, acc[1][3]);
            acc[2][0] = ffma2(a23.x, b0, acc[2][0]);
            acc[2][1] = ffma2(a23.x, b1p, acc[2][1]);
            acc[2][2] = ffma2(a23.x, b2p, acc[2][2]);
            acc[2][3] = ffma2(a23.x, b3p, acc[2][3]);
            acc[3][0] = ffma2(a23.y, b0, acc[3][0]);
            acc[3][1] = ffma2(a23.y, b1p, acc[3][1]);
            acc[3][2] = ffma2(a23.y, b2p, acc[3][2]);
            acc[3][3] = ffma2(a23.y, b3p, acc[3][3]);
        }
        __syncthreads();
    }
#pragma unroll
    for (int mp = 0; mp < 4; mp++)
#pragma unroll
        for (int j = 0; j < 4; j++) {
            float2 v = upk2(acc[mp][j]);
            int m = m0 + tm0 + mp * 2;
            int nn = n0 + tn0 + j;
            if (doAtomic) {
                atomicAdd(&C[(long)m * ldc + nn], v.x);
                atomicAdd(&C[(long)(m + 1) * ldc + nn], v.y);
            } else {
                float bb = bias ? bias[nn] : 0.f;
                C[(long)m * ldc + nn] = v.x + bb;
                C[(long)(m + 1) * ldc + nn] = v.y + bb;
            }
        }
}

// ---------------- small helpers ----------------
__global__ void bsum_kernel(const float* __restrict__ proj, float* __restrict__ bs) {
    int idx = blockIdx.x * 256 + threadIdx.x;
    if (idx < SEQ * 64) {
        int q = idx >> 6, j = idx & 63;
        float s = 0.f;
#pragma unroll
        for (int nn = 0; nn < 8; nn++) s += proj[q * 2560 + 512 + nn * 64 + j];
        bs[idx] = s;
    }
}

__global__ void reshape_wk(const float* __restrict__ wk, float* __restrict__ out) {
    for (int o = blockIdx.x * blockDim.x + threadIdx.x; o < 4096 * 512;
         o += gridDim.x * blockDim.x) {
        int ij = o >> 9, nk = o & 511;
        int n = nk >> 6, k = nk & 63;
        int i = ij >> 6, j = ij & 63;
        out[o] = wk[n * 262144 + i * 4096 + j * 64 + k];
    }
}

__global__ void dT_kernel(const float* __restrict__ proj, float* __restrict__ dT) {
    int idx = blockIdx.x * 256 + threadIdx.x;
    if (idx < NH * 64 * SEQ) {
        int n = idx / (64 * SEQ);
        int rem = idx - n * 64 * SEQ;
        int h = rem / SEQ, p = rem % SEQ;
        dT[idx] = proj[p * 2560 + 1536 + n * 64 + h];
    }
}

__global__ void zero_kernel(float* p, int n) {
    int i = blockIdx.x * 256 + threadIdx.x;
    if (i < n) p[i] = 0.f;
}

__global__ void zscale_kernel(float* __restrict__ zb, const float* __restrict__ Z) {
    int idx = blockIdx.x * 256 + threadIdx.x;
    if (idx < SEQ * 512) {
        int r = idx >> 9, c = idx & 511;
        int n = c >> 6;
        zb[idx] = zb[idx] / Z[n * SEQ + r];
    }
}

// ---------------- fused score+exp+F kernel ----------------
// grid (r=192, n=8), 192 threads; thread p computes F[n,r,p,0:64], Z contrib.
__global__ __launch_bounds__(192, 2) void attn_kernel(
    const float* __restrict__ proj, const float* __restrict__ step2,
    float* __restrict__ F, float* __restrict__ Z)
{
    extern __shared__ float sm[];
    float* St = sm;            // [q][i] 192x64
    float* Es = sm + 12288;    // [q][g] 192x64
    __shared__ float zred[8];
    int r = blockIdx.x, n = blockIdx.y, p = threadIdx.x;

    {
        const float4* src = (const float4*)(step2 + (long)r * 12288);
        float4* dst = (float4*)St;
        for (int i = p; i < 3072; i += 192) dst[i] = src[i];
        for (int i = p; i < 3072; i += 192) {
            int q = i >> 4, g4 = i & 15;
            ((float4*)Es)[i] = *(const float4*)(proj + q * 2560 + 2048 + n * 64 + g4 * 4);
        }
    }
    float a[64];
#pragma unroll
    for (int i4 = 0; i4 < 16; i4++) {
        float4 v = *(const float4*)(proj + p * 2560 + n * 64 + i4 * 4);
        a[i4 * 4] = v.x; a[i4 * 4 + 1] = v.y; a[i4 * 4 + 2] = v.z; a[i4 * 4 + 3] = v.w;
    }
    __syncthreads();

    u64t F2[32];
#pragma unroll
    for (int j = 0; j < 32; j++) F2[j] = 0ULL;
    float Zacc = 0.f;

    for (int q = 0; q < 192; q++) {
        float ex;
        if (q > p) {
            float s = 0.f;
#pragma unroll
            for (int i4 = 0; i4 < 16; i4++) {
                float4 sv = *(const float4*)&St[q * 64 + i4 * 4];
                s += a[i4 * 4] * sv.x + a[i4 * 4 + 1] * sv.y
                   + a[i4 * 4 + 2] * sv.z + a[i4 * 4 + 3] * sv.w;
            }
            ex = fexp(s * 0.015625f);
        } else {
            ex = 1.0f;   // exp(1e-6/64) == 1.0f in fp32
        }
        Zacc += ex;
        u64t exd = pk2(ex, ex);
#pragma unroll
        for (int j2 = 0; j2 < 16; j2++) {
            ulonglong2 ev = *(const ulonglong2*)&Es[q * 64 + j2 * 4];
            F2[j2 * 2]     = ffma2(exd, ev.x, F2[j2 * 2]);
            F2[j2 * 2 + 1] = ffma2(exd, ev.y, F2[j2 * 2 + 1]);
        }
    }

    u64t* Fp = (u64t*)(F + (((long)(n * SEQ + r)) * SEQ + p) * 64);
#pragma unroll
    for (int j = 0; j < 32; j++) Fp[j] = F2[j];

    // Z block reduction
    float zw = Zacc;
    for (int o = 16; o; o >>= 1) zw += __shfl_down_sync(~0u, zw, o);
    if ((p & 31) == 0) zred[p >> 5] = zw;
    __syncthreads();
    if (p == 0) {
        float zt = 0.f;
        for (int w = 0; w < 6; w++) zt += zred[w];
        Z[n * SEQ + r] = zt;
    }
}

extern "C" void kernel_launch(void* const* d_in, const int* in_sizes, int n_in,
                              void* d_out, int out_size) {
    const float* x       = (const float*)d_in[0];
    const float* ln_w    = (const float*)d_in[1];
    const float* ln_b    = (const float*)d_in[2];
    const float* W_abcde = (const float*)d_in[3];
    const float* b_abcde = (const float*)d_in[4];
    const float* W_K     = (const float*)d_in[5];
    const float* W_V     = (const float*)d_in[6];
    const float* W_out   = (const float*)d_in[7];
    const float* b_out   = (const float*)d_in[8];
    float* out = (float*)d_out;

    float *xn, *proj, *bsum, *wkr, *step1, *step2, *dT, *F, *Z, *U, *zb;
    cudaGetSymbolAddress((void**)&xn, g_xn);
    cudaGetSymbolAddress((void**)&proj, g_proj);
    cudaGetSymbolAddress((void**)&bsum, g_bsum);
    cudaGetSymbolAddress((void**)&wkr, g_wkr);
    cudaGetSymbolAddress((void**)&step1, g_step1);
    cudaGetSymbolAddress((void**)&step2, g_step2);
    cudaGetSymbolAddress((void**)&dT, g_dT);
    cudaGetSymbolAddress((void**)&F, g_F);
    cudaGetSymbolAddress((void**)&Z, g_Z);
    cudaGetSymbolAddress((void**)&U, g_U);
    cudaGetSymbolAddress((void**)&zb, g_zbuf);

    cudaFuncSetAttribute(attn_kernel, cudaFuncAttributeMaxDynamicSharedMemorySize, 98304);

    // 1. LayerNorm
    ln_kernel<<<SEQ, 256>>>(x, ln_w, ln_b, xn);
    // 2. W_K reshape -> [ij][nk]
    reshape_wk<<<2048, 256>>>(W_K, wkr);
    // 3. proj = xn @ W_abcde^T + b  (M=192,N=2560,K=512)
    gemm_kernel<<<dim3(40, 3, 1), 128>>>(xn, 512, 0, 0, W_abcde, 512, 1, 0, 0,
                                         proj, 2560, 0, 0, b_abcde, 512, 1, 1, 0);
    // 4. Bsum
    bsum_kernel<<<48, 256>>>(proj, bsum);
    // 5. dT
    dT_kernel<<<(NH * 64 * SEQ + 255) / 256, 256>>>(proj, dT);
    // 6. step1 = c @ wkr^T  (M=192,N=4096,K=512)
    gemm_kernel<<<dim3(64, 3, 1), 128>>>(proj + 1024, 2560, 0, 0, wkr, 512, 1, 0, 0,
                                         step1, 4096, 0, 0, 0, 512, 1, 1, 0);
    // 7. step2[r][q][i] = Bsum @ step1_r^T  (batch r=192, M=192,N=64,K=64)
    gemm_kernel<<<dim3(1, 3, 192), 128>>>(bsum, 64, 0, 0, step1, 64, 1, 4096, 0,
                                          step2, 64, 12288, 0, 0, 64, 192, 1, 0);
    // 8. fused scores/exp/F/Z
    attn_kernel<<<dim3(192, 8), 192, 98304>>>(proj, step2, F, Z);
    // 9. U[n,r] = dT_n @ F_{n,r}  (batch b1=r(192), b2=n(8); M=64,N=64,K=192)
    gemm_kernel<<<dim3(1, 1, 1536), 128>>>(dT, 192, 0, 12288,
                                           F, 1, 64, 12288, 2359296,
                                           U, 64, 4096, 786432, 0, 192, 192, 1, 0);
    // 10. zero z, then z[r, n*64+f] = U_n[r,:] . W_V_n[:,f]  (k-split atomic)
    zero_kernel<<<(SEQ * 512 + 255) / 256, 256>>>(zb, SEQ * 512);
    gemm_kernel<<<dim3(1, 3, 64), 128>>>(U, 4096, 786432, 0,
                                         W_V, 1, 64, 262144, 0,
                                         zb, 512, 64, 0, 0, 4096, 8, 8, 1);
    // 11. divide by softmax denominator
    zscale_kernel<<<(SEQ * 512 + 255) / 256, 256>>>(zb, Z);
    // 12. out = z @ W_out^T + b_out  (M=192,N=512,K=512)
    gemm_kernel<<<dim3(8, 3, 1), 128>>>(zb, 512, 0, 0, W_out, 512, 1, 0, 0,
                                        out, 512, 0, 0, b_out, 512, 1, 1, 0);
}

// round 3
// speedup vs baseline: 1.1107x; 1.1107x over previous
#include <cuda_runtime.h>

#define SEQ 192
#define NH 8

__device__ float g_xn[SEQ * 512];
__device__ float g_proj[SEQ * 2560];
__device__ float g_bsum[SEQ * 64];
__device__ float g_wkr[4096 * 512];
__device__ float g_step1[SEQ * 4096];
__device__ float g_step2[SEQ * SEQ * 64];
__device__ float g_dT[NH * 64 * SEQ];
__device__ float g_Epre[NH * SEQ * 64];
__device__ float g_F[NH * SEQ * SEQ * 64];
__device__ float g_Z[NH * SEQ];
__device__ float g_U[NH * SEQ * 4096];
__device__ float g_zbuf[SEQ * 512];

typedef unsigned long long u64t;

__device__ __forceinline__ u64t pk2(float lo, float hi) {
    u64t d; asm("mov.b64 %0, {%1, %2};" : "=l"(d) : "f"(lo), "f"(hi)); return d;
}
__device__ __forceinline__ float2 upk2(u64t d) {
    float2 r; asm("mov.b64 {%0, %1}, %2;" : "=f"(r.x), "=f"(r.y) : "l"(d)); return r;
}
__device__ __forceinline__ u64t ffma2(u64t a, u64t b, u64t c) {
    u64t d; asm("fma.rn.f32x2 %0, %1, %2, %3;" : "=l"(d) : "l"(a), "l"(b), "l"(c)); return d;
}

__device__ __forceinline__ float fexp(float x) {
    float t = fmaf(x, 1.4426950408889634f, 12582912.0f);
    float kf = t - 12582912.0f;
    int ki = (int)kf;
    float r = fmaf(kf, -0.69314718055994531f, x);
    float p = 1.38888889e-3f;
    p = fmaf(p, r, 8.33333333e-3f);
    p = fmaf(p, r, 4.16666667e-2f);
    p = fmaf(p, r, 1.66666667e-1f);
    p = fmaf(p, r, 0.5f);
    p = fmaf(p, r, 1.0f);
    p = fmaf(p, r, 1.0f);
    return p * __int_as_float((ki + 127) << 23);
}

__global__ __launch_bounds__(256) void ln_kernel(const float* __restrict__ x,
                                                 const float* __restrict__ w,
                                                 const float* __restrict__ b,
                                                 float* __restrict__ xn) {
    __shared__ float rs[256], rq[256];
    int row = blockIdx.x, tid = threadIdx.x;
    float v0 = x[row * 512 + tid], v1 = x[row * 512 + 256 + tid];
    rs[tid] = v0 + v1;
    rq[tid] = v0 * v0 + v1 * v1;
    __syncthreads();
    for (int s = 128; s >= 32; s >>= 1) {
        if (tid < s) { rs[tid] += rs[tid + s]; rq[tid] += rq[tid + s]; }
        __syncthreads();
    }
    if (tid < 32) {
        float a = rs[tid], q = rq[tid];
        for (int o = 16; o; o >>= 1) {
            a += __shfl_down_sync(~0u, a, o);
            q += __shfl_down_sync(~0u, q, o);
        }
        if (!tid) { rs[0] = a; rq[0] = q; }
    }
    __syncthreads();
    float mu = rs[0] * (1.f / 512.f);
    float var = rq[0] * (1.f / 512.f) - mu * mu;
    float is = rsqrtf(var + 1e-5f);
    xn[row * 512 + tid]       = (v0 - mu) * is * w[tid]       + b[tid];
    xn[row * 512 + 256 + tid] = (v1 - mu) * is * w[256 + tid] + b[256 + tid];
}

__global__ __launch_bounds__(128) void gemm_kernel(
    const float* __restrict__ A, int lda, long sA1, long sA2,
    const float* __restrict__ B, int ldbn, int ldbk, long sB1, long sB2,
    float* __restrict__ C, int ldc, long sC1, long sC2,
    const float* __restrict__ bias,
    int K, int nb1, int kSplits, int doAtomic)
{
    __shared__ float Ast[16][68];
    __shared__ float Bst[16][68];
    int z = blockIdx.z;
    int kz = z % kSplits;
    int t = z / kSplits;
    int b1 = t % nb1, b2 = t / nb1;
    A += b1 * sA1 + b2 * sA2;
    B += b1 * sB1 + b2 * sB2;
    C += b1 * sC1 + b2 * sC2;
    const int kPer = K / kSplits;
    const int k0 = kz * kPer, k1 = k0 + kPer;
    const int m0 = blockIdx.y * 64;
    const int n0 = blockIdx.x * 64;
    const int tid = threadIdx.x;
    const int tn0 = (tid & 15) * 4;
    const int tm0 = (tid >> 4) * 8;

    u64t acc[4][4];
#pragma unroll
    for (int i = 0; i < 4; i++)
#pragma unroll
        for (int j = 0; j < 4; j++) acc[i][j] = 0ULL;

    for (int kk = k0; kk < k1; kk += 16) {
#pragma unroll
        for (int j = 0; j < 2; j++) {
            int idx = tid + j * 128;
            int m = idx >> 2, kq = (idx & 3) * 4;
            float4 v = *(const float4*)(A + (long)(m0 + m) * lda + kk + kq);
            Ast[kq + 0][m] = v.x; Ast[kq + 1][m] = v.y;
            Ast[kq + 2][m] = v.z; Ast[kq + 3][m] = v.w;
        }
        if (ldbk == 1) {
#pragma unroll
            for (int j = 0; j < 2; j++) {
                int idx = tid + j * 128;
                int nn = idx >> 2, kq = (idx & 3) * 4;
                float4 v = *(const float4*)(B + (long)(n0 + nn) * ldbn + kk + kq);
                Bst[kq + 0][nn] = v.x; Bst[kq + 1][nn] = v.y;
                Bst[kq + 2][nn] = v.z; Bst[kq + 3][nn] = v.w;
            }
        } else {
#pragma unroll
            for (int j = 0; j < 8; j++) {
                int idx = tid + j * 128;
                int nn = idx & 63, k = idx >> 6;
                Bst[k][nn] = B[(long)(kk + k) * ldbk + (long)(n0 + nn) * ldbn];
            }
        }
        __syncthreads();
#pragma unroll
        for (int k = 0; k < 16; k++) {
            ulonglong2 a01 = *(const ulonglong2*)&Ast[k][tm0];
            ulonglong2 a23 = *(const ulonglong2*)&Ast[k][tm0 + 4];
            float4 bv = *(const float4*)&Bst[k][tn0];
            u64t b0 = pk2(bv.x, bv.x), b1p = pk2(bv.y, bv.y);
            u64t b2p = pk2(bv.z, bv.z), b3p = pk2(bv.w, bv.w);
            acc[0][0] = ffma2(a01.x, b0, acc[0][0]);
            acc[0][1] = ffma2(a01.x, b1p, acc[0][1]);
            acc[0][2] = ffma2(a01.x, b2p, acc[0][2]);
            acc[0][3] = ffma2(a01.x, b3p, acc[0][3]);
            acc[1][0] = ffma2(a01.y, b0, acc[1][0]);
            acc[1][1] = ffma2(a01.y, b1p, acc[1][1]);
            acc[1][2] = ffma2(a01.y, b2p, acc[1][2]);
            acc[1][3] = ffma2(a01.y, b3p, acc[1][3]);
            acc[2][0] = ffma2(a23.x, b0, acc[2][0]);
            acc[2][1] = ffma2(a23.x, b1p, acc[2][1]);
            acc[2][2] = ffma2(a23.x, b2p, acc[2][2]);
            acc[2][3] = ffma2(a23.x, b3p, acc[2][3]);
            acc[3][0] = ffma2(a23.y, b0, acc[3][0]);
            acc[3][1] = ffma2(a23.y, b1p, acc[3][1]);
            acc[3][2] = ffma2(a23.y, b2p, acc[3][2]);
            acc[3][3] = ffma2(a23.y, b3p, acc[3][3]);
        }
        __syncthreads();
    }
#pragma unroll
    for (int mp = 0; mp < 4; mp++)
#pragma unroll
        for (int j = 0; j < 4; j++) {
            float2 v = upk2(acc[mp][j]);
            int m = m0 + tm0 + mp * 2;
            int nn = n0 + tn0 + j;
            if (doAtomic) {
                atomicAdd(&C[(long)m * ldc + nn], v.x);
                atomicAdd(&C[(long)(m + 1) * ldc + nn], v.y);
            } else {
                float bb = bias ? bias[nn] : 0.f;
                C[(long)m * ldc + nn] = v.x + bb;
                C[(long)(m + 1) * ldc + nn] = v.y + bb;
            }
        }
}

__global__ void bsum_kernel(const float* __restrict__ proj, float* __restrict__ bs) {
    int idx = blockIdx.x * 256 + threadIdx.x;
    if (idx < SEQ * 64) {
        int q = idx >> 6, j = idx & 63;
        float s = 0.f;
#pragma unroll
        for (int nn = 0; nn < 8; nn++) s += proj[q * 2560 + 512 + nn * 64 + j];
        bs[idx] = s;
    }
}

__global__ void reshape_wk(const float* __restrict__ wk, float* __restrict__ out) {
    for (int o = blockIdx.x * blockDim.x + threadIdx.x; o < 4096 * 512;
         o += gridDim.x * blockDim.x) {
        int ij = o >> 9, nk = o & 511;
        int n = nk >> 6, k = nk & 63;
        int i = ij >> 6, j = ij & 63;
        out[o] = wk[n * 262144 + i * 4096 + j * 64 + k];
    }
}

__global__ void dT_kernel(const float* __restrict__ proj, float* __restrict__ dT) {
    int idx = blockIdx.x * 256 + threadIdx.x;
    if (idx < NH * 64 * SEQ) {
        int n = idx / (64 * SEQ);
        int rem = idx - n * 64 * SEQ;
        int h = rem / SEQ, p = rem % SEQ;
        dT[idx] = proj[p * 2560 + 1536 + n * 64 + h];
    }
}

// inclusive prefix over q of e_n[q][g]  (r-independent masked contribution)
__global__ void epre_kernel(const float* __restrict__ proj, float* __restrict__ Epre) {
    int n = blockIdx.x, g = threadIdx.x;
    float run = 0.f;
    for (int p = 0; p < SEQ; p++) {
        run += proj[p * 2560 + 2048 + n * 64 + g];
        Epre[((long)n * SEQ + p) * 64 + g] = run;
    }
}

__global__ void zero_kernel(float* p, int n) {
    int i = blockIdx.x * 256 + threadIdx.x;
    if (i < n) p[i] = 0.f;
}

__global__ void zscale_kernel(float* __restrict__ zb, const float* __restrict__ Z) {
    int idx = blockIdx.x * 256 + threadIdx.x;
    if (idx < SEQ * 512) {
        int r = idx >> 9, c = idx & 511;
        int n = c >> 6;
        zb[idx] = zb[idx] / Z[n * SEQ + r];
    }
}

// fused score+exp+F; masked (q<=p) region handled by Epre prefix init.
__global__ __launch_bounds__(192, 2) void attn_kernel(
    const float* __restrict__ proj, const float* __restrict__ step2,
    const float* __restrict__ Epre,
    float* __restrict__ F, float* __restrict__ Z)
{
    extern __shared__ float sm[];
    float* St = sm;            // [q][i] 192x64
    float* Es = sm + 12288;    // [q][g] 192x64
    __shared__ float zred[8];
    int r = blockIdx.x, n = blockIdx.y, p = threadIdx.x;

    {
        const float4* src = (const float4*)(step2 + (long)r * 12288);
        for (int i = p; i < 3072; i += 192) ((float4*)St)[i] = src[i];
        for (int i = p; i < 3072; i += 192) {
            int q = i >> 4, g4 = i & 15;
            ((float4*)Es)[i] = *(const float4*)(proj + q * 2560 + 2048 + n * 64 + g4 * 4);
        }
    }
    u64t a2[32];
#pragma unroll
    for (int i = 0; i < 32; i++)
        a2[i] = *(const u64t*)(proj + p * 2560 + n * 64 + 2 * i);
    __syncthreads();

    u64t F2[32];
    {
        const u64t* Ep = (const u64t*)(Epre + ((long)n * SEQ + p) * 64);
#pragma unroll
        for (int j = 0; j < 32; j++) F2[j] = Ep[j];
    }
    float Zacc = (float)(p + 1);

    for (int q = 0; q < 192; q++) {
        if (q > p) {
            const ulonglong2* Stp = (const ulonglong2*)&St[q * 64];
            u64t sA = 0ULL, sB = 0ULL;
#pragma unroll
            for (int j = 0; j < 16; j++) {
                ulonglong2 sv = Stp[j];
                sA = ffma2(a2[2 * j], sv.x, sA);
                sB = ffma2(a2[2 * j + 1], sv.y, sB);
            }
            float2 fa = upk2(sA), fb = upk2(sB);
            float ex = fexp((fa.x + fa.y + fb.x + fb.y) * 0.015625f);
            Zacc += ex;
            u64t exd = pk2(ex, ex);
            const ulonglong2* Ep2 = (const ulonglong2*)&Es[q * 64];
#pragma unroll
            for (int j2 = 0; j2 < 16; j2++) {
                ulonglong2 ev = Ep2[j2];
                F2[2 * j2]     = ffma2(exd, ev.x, F2[2 * j2]);
                F2[2 * j2 + 1] = ffma2(exd, ev.y, F2[2 * j2 + 1]);
            }
        }
    }

    u64t* Fp = (u64t*)(F + (((long)(n * SEQ + r)) * SEQ + p) * 64);
#pragma unroll
    for (int j = 0; j < 32; j++) Fp[j] = F2[j];

    float zw = Zacc;
    for (int o = 16; o; o >>= 1) zw += __shfl_down_sync(~0u, zw, o);
    if ((p & 31) == 0) zred[p >> 5] = zw;
    __syncthreads();
    if (p == 0) {
        float zt = 0.f;
        for (int w = 0; w < 6; w++) zt += zred[w];
        Z[n * SEQ + r] = zt;
    }
}

extern "C" void kernel_launch(void* const* d_in, const int* in_sizes, int n_in,
                              void* d_out, int out_size) {
    const float* x       = (const float*)d_in[0];
    const float* ln_w    = (const float*)d_in[1];
    const float* ln_b    = (const float*)d_in[2];
    const float* W_abcde = (const float*)d_in[3];
    const float* b_abcde = (const float*)d_in[4];
    const float* W_K     = (const float*)d_in[5];
    const float* W_V     = (const float*)d_in[6];
    const float* W_out   = (const float*)d_in[7];
    const float* b_out   = (const float*)d_in[8];
    float* out = (float*)d_out;

    float *xn, *proj, *bsum, *wkr, *step1, *step2, *dT, *Epre, *F, *Z, *U, *zb;
    cudaGetSymbolAddress((void**)&xn, g_xn);
    cudaGetSymbolAddress((void**)&proj, g_proj);
    cudaGetSymbolAddress((void**)&bsum, g_bsum);
    cudaGetSymbolAddress((void**)&wkr, g_wkr);
    cudaGetSymbolAddress((void**)&step1, g_step1);
    cudaGetSymbolAddress((void**)&step2, g_step2);
    cudaGetSymbolAddress((void**)&dT, g_dT);
    cudaGetSymbolAddress((void**)&Epre, g_Epre);
    cudaGetSymbolAddress((void**)&F, g_F);
    cudaGetSymbolAddress((void**)&Z, g_Z);
    cudaGetSymbolAddress((void**)&U, g_U);
    cudaGetSymbolAddress((void**)&zb, g_zbuf);

    cudaFuncSetAttribute(attn_kernel, cudaFuncAttributeMaxDynamicSharedMemorySize, 98304);

    ln_kernel<<<SEQ, 256>>>(x, ln_w, ln_b, xn);
    reshape_wk<<<2048, 256>>>(W_K, wkr);
    gemm_kernel<<<dim3(40, 3, 1), 128>>>(xn, 512, 0, 0, W_abcde, 512, 1, 0, 0,
                                         proj, 2560, 0, 0, b_abcde, 512, 1, 1, 0);
    bsum_kernel<<<48, 256>>>(proj, bsum);
    dT_kernel<<<(NH * 64 * SEQ + 255) / 256, 256>>>(proj, dT);
    epre_kernel<<<NH, 64>>>(proj, Epre);
    gemm_kernel<<<dim3(64, 3, 1), 128>>>(proj + 1024, 2560, 0, 0, wkr, 512, 1, 0, 0,
                                         step1, 4096, 0, 0, 0, 512, 1, 1, 0);
    gemm_kernel<<<dim3(1, 3, 192), 128>>>(bsum, 64, 0, 0, step1, 64, 1, 4096, 0,
                                          step2, 64, 12288, 0, 0, 64, 192, 1, 0);
    attn_kernel<<<dim3(192, 8), 192, 98304>>>(proj, step2, Epre, F, Z);
    gemm_kernel<<<dim3(1, 1, 1536), 128>>>(dT, 192, 0, 12288,
                                           F, 1, 64, 12288, 2359296,
                                           U, 64, 4096, 786432, 0, 192, 192, 1, 0);
    zero_kernel<<<(SEQ * 512 + 255) / 256, 256>>>(zb, SEQ * 512);
    gemm_kernel<<<dim3(1, 3, 64), 128>>>(U, 4096, 786432, 0,
                                         W_V, 1, 64, 262144, 0,
                                         zb, 512, 64, 0, 0, 4096, 8, 8, 1);
    zscale_kernel<<<(SEQ * 512 + 255) / 256, 256>>>(zb, Z);
    gemm_kernel<<<dim3(8, 3, 1), 128>>>(zb, 512, 0, 0, W_out, 512, 1, 0, 0,
                                        out, 512, 0, 0, b_out, 512, 1, 1, 0);
}

// round 4
// speedup vs baseline: 1.2225x; 1.1006x over previous
#include <cuda_runtime.h>

#define SEQ 192
#define NH 8

__device__ float g_xn[SEQ * 512];
__device__ float g_proj[SEQ * 2560];
__device__ float g_bsum[SEQ * 64];
__device__ float g_wkr[4096 * 512];
__device__ float g_step1[SEQ * 4096];
__device__ float g_step2[SEQ * SEQ * 64];
__device__ float g_dT[NH * 64 * SEQ];
__device__ float g_Epre[NH * SEQ * 64];
__device__ float g_F[NH * SEQ * SEQ * 64];
__device__ float g_Z[NH * SEQ];
__device__ float g_U[NH * SEQ * 4096];
__device__ float g_zbuf[SEQ * 512];

typedef unsigned long long u64t;

__device__ __forceinline__ u64t pk2(float lo, float hi) {
    u64t d; asm("mov.b64 %0, {%1, %2};" : "=l"(d) : "f"(lo), "f"(hi)); return d;
}
__device__ __forceinline__ float2 upk2(u64t d) {
    float2 r; asm("mov.b64 {%0, %1}, %2;" : "=f"(r.x), "=f"(r.y) : "l"(d)); return r;
}
__device__ __forceinline__ u64t ffma2(u64t a, u64t b, u64t c) {
    u64t d; asm("fma.rn.f32x2 %0, %1, %2, %3;" : "=l"(d) : "l"(a), "l"(b), "l"(c)); return d;
}

__device__ __forceinline__ float fexp(float x) {
    float t = fmaf(x, 1.4426950408889634f, 12582912.0f);
    float kf = t - 12582912.0f;
    int ki = (int)kf;
    float r = fmaf(kf, -0.69314718055994531f, x);
    float p = 1.38888889e-3f;
    p = fmaf(p, r, 8.33333333e-3f);
    p = fmaf(p, r, 4.16666667e-2f);
    p = fmaf(p, r, 1.66666667e-1f);
    p = fmaf(p, r, 0.5f);
    p = fmaf(p, r, 1.0f);
    p = fmaf(p, r, 1.0f);
    return p * __int_as_float((ki + 127) << 23);
}

__global__ __launch_bounds__(256) void ln_kernel(const float* __restrict__ x,
                                                 const float* __restrict__ w,
                                                 const float* __restrict__ b,
                                                 float* __restrict__ xn) {
    __shared__ float rs[256], rq[256];
    int row = blockIdx.x, tid = threadIdx.x;
    float v0 = x[row * 512 + tid], v1 = x[row * 512 + 256 + tid];
    rs[tid] = v0 + v1;
    rq[tid] = v0 * v0 + v1 * v1;
    __syncthreads();
    for (int s = 128; s >= 32; s >>= 1) {
        if (tid < s) { rs[tid] += rs[tid + s]; rq[tid] += rq[tid + s]; }
        __syncthreads();
    }
    if (tid < 32) {
        float a = rs[tid], q = rq[tid];
        for (int o = 16; o; o >>= 1) {
            a += __shfl_down_sync(~0u, a, o);
            q += __shfl_down_sync(~0u, q, o);
        }
        if (!tid) { rs[0] = a; rq[0] = q; }
    }
    __syncthreads();
    float mu = rs[0] * (1.f / 512.f);
    float var = rq[0] * (1.f / 512.f) - mu * mu;
    float is = rsqrtf(var + 1e-5f);
    xn[row * 512 + tid]       = (v0 - mu) * is * w[tid]       + b[tid];
    xn[row * 512 + 256 + tid] = (v1 - mu) * is * w[256 + tid] + b[256 + tid];
}

// 64x64 tile GEMM with register-prefetch double buffering.
__global__ __launch_bounds__(128) void gemm_kernel(
    const float* __restrict__ A, int lda, long sA1, long sA2,
    const float* __restrict__ B, int ldbn, int ldbk, long sB1, long sB2,
    float* __restrict__ C, int ldc, long sC1, long sC2,
    const float* __restrict__ bias,
    int K, int nb1, int kSplits, int doAtomic)
{
    __shared__ float Ast[16][68];
    __shared__ float Bst[16][68];
    int z = blockIdx.z;
    int kz = z % kSplits;
    int t = z / kSplits;
    int b1 = t % nb1, b2 = t / nb1;
    A += b1 * sA1 + b2 * sA2;
    B += b1 * sB1 + b2 * sB2;
    C += b1 * sC1 + b2 * sC2;
    const int kPer = K / kSplits;
    const int k0 = kz * kPer, k1 = k0 + kPer;
    const int m0 = blockIdx.y * 64;
    const int n0 = blockIdx.x * 64;
    const int tid = threadIdx.x;
    const int tn0 = (tid & 15) * 4;
    const int tm0 = (tid >> 4) * 8;
    const int pam = tid >> 2, pak = (tid & 3) * 4;       // A prefetch coords (j=0)
    const int pbn = tid & 63;                             // scalar-B col

    u64t acc[4][4];
#pragma unroll
    for (int i = 0; i < 4; i++)
#pragma unroll
        for (int j = 0; j < 4; j++) acc[i][j] = 0ULL;

    float4 pa[2], pb[2];
    float pbs[8];

    // prefetch first tile
#pragma unroll
    for (int j = 0; j < 2; j++) {
        int idx = tid + j * 128;
        pa[j] = *(const float4*)(A + (long)(m0 + (idx >> 2)) * lda + k0 + (idx & 3) * 4);
    }
    if (ldbk == 1) {
#pragma unroll
        for (int j = 0; j < 2; j++) {
            int idx = tid + j * 128;
            pb[j] = *(const float4*)(B + (long)(n0 + (idx >> 2)) * ldbn + k0 + (idx & 3) * 4);
        }
    } else {
#pragma unroll
        for (int j = 0; j < 8; j++) {
            int k = (tid + j * 128) >> 6;
            pbs[j] = B[(long)(k0 + k) * ldbk + (long)(n0 + pbn) * ldbn];
        }
    }

    for (int kk = k0; kk < k1; kk += 16) {
        // store prefetched regs into smem
#pragma unroll
        for (int j = 0; j < 2; j++) {
            int idx = tid + j * 128;
            int m = idx >> 2, kq = (idx & 3) * 4;
            Ast[kq + 0][m] = pa[j].x; Ast[kq + 1][m] = pa[j].y;
            Ast[kq + 2][m] = pa[j].z; Ast[kq + 3][m] = pa[j].w;
        }
        if (ldbk == 1) {
#pragma unroll
            for (int j = 0; j < 2; j++) {
                int idx = tid + j * 128;
                int nn = idx >> 2, kq = (idx & 3) * 4;
                Bst[kq + 0][nn] = pb[j].x; Bst[kq + 1][nn] = pb[j].y;
                Bst[kq + 2][nn] = pb[j].z; Bst[kq + 3][nn] = pb[j].w;
            }
        } else {
#pragma unroll
            for (int j = 0; j < 8; j++) {
                int idx = tid + j * 128;
                Bst[idx >> 6][idx & 63] = pbs[j];
            }
        }
        __syncthreads();

        // prefetch next tile
        if (kk + 16 < k1) {
            int kn = kk + 16;
#pragma unroll
            for (int j = 0; j < 2; j++) {
                int idx = tid + j * 128;
                pa[j] = *(const float4*)(A + (long)(m0 + (idx >> 2)) * lda + kn + (idx & 3) * 4);
            }
            if (ldbk == 1) {
#pragma unroll
                for (int j = 0; j < 2; j++) {
                    int idx = tid + j * 128;
                    pb[j] = *(const float4*)(B + (long)(n0 + (idx >> 2)) * ldbn + kn + (idx & 3) * 4);
                }
            } else {
#pragma unroll
                for (int j = 0; j < 8; j++) {
                    int k = (tid + j * 128) >> 6;
                    pbs[j] = B[(long)(kn + k) * ldbk + (long)(n0 + pbn) * ldbn];
                }
            }
        }

#pragma unroll
        for (int k = 0; k < 16; k++) {
            ulonglong2 a01 = *(const ulonglong2*)&Ast[k][tm0];
            ulonglong2 a23 = *(const ulonglong2*)&Ast[k][tm0 + 4];
            float4 bv = *(const float4*)&Bst[k][tn0];
            u64t b0 = pk2(bv.x, bv.x), b1p = pk2(bv.y, bv.y);
            u64t b2p = pk2(bv.z, bv.z), b3p = pk2(bv.w, bv.w);
            acc[0][0] = ffma2(a01.x, b0, acc[0][0]);
            acc[0][1] = ffma2(a01.x, b1p, acc[0][1]);
            acc[0][2] = ffma2(a01.x, b2p, acc[0][2]);
            acc[0][3] = ffma2(a01.x, b3p, acc[0][3]);
            acc[1][0] = ffma2(a01.y, b0, acc[1][0]);
            acc[1][1] = ffma2(a01.y, b1p, acc[1][1]);
            acc[1][2] = ffma2(a01.y, b2p, acc[1][2]);
            acc[1][3] = ffma2(a01.y, b3p, acc[1][3]);
            acc[2][0] = ffma2(a23.x, b0, acc[2][0]);
            acc[2][1] = ffma2(a23.x, b1p, acc[2][1]);
            acc[2][2] = ffma2(a23.x, b2p, acc[2][2]);
            acc[2][3] = ffma2(a23.x, b3p, acc[2][3]);
            acc[3][0] = ffma2(a23.y, b0, acc[3][0]);
            acc[3][1] = ffma2(a23.y, b1p, acc[3][1]);
            acc[3][2] = ffma2(a23.y, b2p, acc[3][2]);
            acc[3][3] = ffma2(a23.y, b3p, acc[3][3]);
        }
        __syncthreads();
    }
#pragma unroll
    for (int mp = 0; mp < 4; mp++)
#pragma unroll
        for (int j = 0; j < 4; j++) {
            float2 v = upk2(acc[mp][j]);
            int m = m0 + tm0 + mp * 2;
            int nn = n0 + tn0 + j;
            if (doAtomic) {
                atomicAdd(&C[(long)m * ldc + nn], v.x);
                atomicAdd(&C[(long)(m + 1) * ldc + nn], v.y);
            } else {
                float bb = bias ? bias[nn] : 0.f;
                C[(long)m * ldc + nn] = v.x + bb;
                C[(long)(m + 1) * ldc + nn] = v.y + bb;
            }
        }
}

__global__ void bsum_kernel(const float* __restrict__ proj, float* __restrict__ bs) {
    int idx = blockIdx.x * 256 + threadIdx.x;
    if (idx < SEQ * 64) {
        int q = idx >> 6, j = idx & 63;
        float s = 0.f;
#pragma unroll
        for (int nn = 0; nn < 8; nn++) s += proj[q * 2560 + 512 + nn * 64 + j];
        bs[idx] = s;
    }
}

__global__ void reshape_wk(const float* __restrict__ wk, float* __restrict__ out) {
    for (int o = blockIdx.x * blockDim.x + threadIdx.x; o < 4096 * 512;
         o += gridDim.x * blockDim.x) {
        int ij = o >> 9, nk = o & 511;
        int n = nk >> 6, k = nk & 63;
        int i = ij >> 6, j = ij & 63;
        out[o] = wk[n * 262144 + i * 4096 + j * 64 + k];
    }
}

__global__ void dT_kernel(const float* __restrict__ proj, float* __restrict__ dT) {
    int idx = blockIdx.x * 256 + threadIdx.x;
    if (idx < NH * 64 * SEQ) {
        int n = idx / (64 * SEQ);
        int rem = idx - n * 64 * SEQ;
        int h = rem / SEQ, p = rem % SEQ;
        dT[idx] = proj[p * 2560 + 1536 + n * 64 + h];
    }
}

__global__ void epre_kernel(const float* __restrict__ proj, float* __restrict__ Epre) {
    int n = blockIdx.x, g = threadIdx.x;
    float run = 0.f;
    for (int p0 = 0; p0 < SEQ; p0 += 8) {
        float v[8];
#pragma unroll
        for (int j = 0; j < 8; j++)
            v[j] = proj[(p0 + j) * 2560 + 2048 + n * 64 + g];
#pragma unroll
        for (int j = 0; j < 8; j++) {
            run += v[j];
            Epre[((long)n * SEQ + p0 + j) * 64 + g] = run;
        }
    }
}

__global__ void zero_kernel(float* p, int n) {
    int i = blockIdx.x * 256 + threadIdx.x;
    if (i < n) p[i] = 0.f;
}

__global__ void fillb_kernel(float* __restrict__ C, const float* __restrict__ bias, int n) {
    int i = blockIdx.x * 256 + threadIdx.x;
    if (i < n) C[i] = bias[i & 511];
}

__global__ void zscale_kernel(float* __restrict__ zb, const float* __restrict__ Z) {
    int idx = blockIdx.x * 256 + threadIdx.x;
    if (idx < SEQ * 512) {
        int r = idx >> 9, c = idx & 511;
        int n = c >> 6;
        zb[idx] = zb[idx] / Z[n * SEQ + r];
    }
}

__global__ __launch_bounds__(192, 2) void attn_kernel(
    const float* __restrict__ proj, const float* __restrict__ step2,
    const float* __restrict__ Epre,
    float* __restrict__ F, float* __restrict__ Z)
{
    extern __shared__ float sm[];
    float* St = sm;
    float* Es = sm + 12288;
    __shared__ float zred[8];
    int r = blockIdx.x, n = blockIdx.y, p = threadIdx.x;

    {
        const float4* src = (const float4*)(step2 + (long)r * 12288);
        for (int i = p; i < 3072; i += 192) ((float4*)St)[i] = src[i];
        for (int i = p; i < 3072; i += 192) {
            int q = i >> 4, g4 = i & 15;
            ((float4*)Es)[i] = *(const float4*)(proj + q * 2560 + 2048 + n * 64 + g4 * 4);
        }
    }
    u64t a2[32];
#pragma unroll
    for (int i = 0; i < 32; i++)
        a2[i] = *(const u64t*)(proj + p * 2560 + n * 64 + 2 * i);
    __syncthreads();

    u64t F2[32];
    {
        const u64t* Ep = (const u64t*)(Epre + ((long)n * SEQ + p) * 64);
#pragma unroll
        for (int j = 0; j < 32; j++) F2[j] = Ep[j];
    }
    float Zacc = (float)(p + 1);

    for (int q = 0; q < 192; q++) {
        if (q > p) {
            const ulonglong2* Stp = (const ulonglong2*)&St[q * 64];
            u64t sA = 0ULL, sB = 0ULL;
#pragma unroll
            for (int j = 0; j < 16; j++) {
                ulonglong2 sv = Stp[j];
                sA = ffma2(a2[2 * j], sv.x, sA);
                sB = ffma2(a2[2 * j + 1], sv.y, sB);
            }
            float2 fa = upk2(sA), fb = upk2(sB);
            float ex = fexp((fa.x + fa.y + fb.x + fb.y) * 0.015625f);
            Zacc += ex;
            u64t exd = pk2(ex, ex);
            const ulonglong2* Ep2 = (const ulonglong2*)&Es[q * 64];
#pragma unroll
            for (int j2 = 0; j2 < 16; j2++) {
                ulonglong2 ev = Ep2[j2];
                F2[2 * j2]     = ffma2(exd, ev.x, F2[2 * j2]);
                F2[2 * j2 + 1] = ffma2(exd, ev.y, F2[2 * j2 + 1]);
            }
        }
    }

    u64t* Fp = (u64t*)(F + (((long)(n * SEQ + r)) * SEQ + p) * 64);
#pragma unroll
    for (int j = 0; j < 32; j++) Fp[j] = F2[j];

    float zw = Zacc;
    for (int o = 16; o; o >>= 1) zw += __shfl_down_sync(~0u, zw, o);
    if ((p & 31) == 0) zred[p >> 5] = zw;
    __syncthreads();
    if (p == 0) {
        float zt = 0.f;
        for (int w = 0; w < 6; w++) zt += zred[w];
        Z[n * SEQ + r] = zt;
    }
}

extern "C" void kernel_launch(void* const* d_in, const int* in_sizes, int n_in,
                              void* d_out, int out_size) {
    const float* x       = (const float*)d_in[0];
    const float* ln_w    = (const float*)d_in[1];
    const float* ln_b    = (const float*)d_in[2];
    const float* W_abcde = (const float*)d_in[3];
    const float* b_abcde = (const float*)d_in[4];
    const float* W_K     = (const float*)d_in[5];
    const float* W_V     = (const float*)d_in[6];
    const float* W_out   = (const float*)d_in[7];
    const float* b_out   = (const float*)d_in[8];
    float* out = (float*)d_out;

    float *xn, *proj, *bsum, *wkr, *step1, *step2, *dT, *Epre, *F, *Z, *U, *zb;
    cudaGetSymbolAddress((void**)&xn, g_xn);
    cudaGetSymbolAddress((void**)&proj, g_proj);
    cudaGetSymbolAddress((void**)&bsum, g_bsum);
    cudaGetSymbolAddress((void**)&wkr, g_wkr);
    cudaGetSymbolAddress((void**)&step1, g_step1);
    cudaGetSymbolAddress((void**)&step2, g_step2);
    cudaGetSymbolAddress((void**)&dT, g_dT);
    cudaGetSymbolAddress((void**)&Epre, g_Epre);
    cudaGetSymbolAddress((void**)&F, g_F);
    cudaGetSymbolAddress((void**)&Z, g_Z);
    cudaGetSymbolAddress((void**)&U, g_U);
    cudaGetSymbolAddress((void**)&zb, g_zbuf);

    cudaFuncSetAttribute(attn_kernel, cudaFuncAttributeMaxDynamicSharedMemorySize, 98304);

    // 1
    ln_kernel<<<SEQ, 256>>>(x, ln_w, ln_b, xn);
    // 2
    reshape_wk<<<2048, 256>>>(W_K, wkr);
    // 3: proj
    gemm_kernel<<<dim3(40, 3, 1), 128>>>(xn, 512, 0, 0, W_abcde, 512, 1, 0, 0,
                                         proj, 2560, 0, 0, b_abcde, 512, 1, 1, 0);
    // 4: step1  <-- ncu profiled slot
    gemm_kernel<<<dim3(64, 3, 1), 128>>>(proj + 1024, 2560, 0, 0, wkr, 512, 1, 0, 0,
                                         step1, 4096, 0, 0, 0, 512, 1, 1, 0);
    // 5
    bsum_kernel<<<48, 256>>>(proj, bsum);
    // 6
    dT_kernel<<<(NH * 64 * SEQ + 255) / 256, 256>>>(proj, dT);
    // 7
    epre_kernel<<<NH, 64>>>(proj, Epre);
    // 8: step2
    gemm_kernel<<<dim3(1, 3, 192), 128>>>(bsum, 64, 0, 0, step1, 64, 1, 4096, 0,
                                          step2, 64, 12288, 0, 0, 64, 192, 1, 0);
    // 9: attn
    attn_kernel<<<dim3(192, 8), 192, 98304>>>(proj, step2, Epre, F, Z);
    // 10: U
    gemm_kernel<<<dim3(1, 1, 1536), 128>>>(dT, 192, 0, 12288,
                                           F, 1, 64, 12288, 2359296,
                                           U, 64, 4096, 786432, 0, 192, 192, 1, 0);
    // 11-13: z
    zero_kernel<<<(SEQ * 512 + 255) / 256, 256>>>(zb, SEQ * 512);
    gemm_kernel<<<dim3(1, 3, 64), 128>>>(U, 4096, 786432, 0,
                                         W_V, 1, 64, 262144, 0,
                                         zb, 512, 64, 0, 0, 4096, 8, 8, 1);
    zscale_kernel<<<(SEQ * 512 + 255) / 256, 256>>>(zb, Z);
    // 14-15: out (bias prefill + k-split atomic for 4x parallelism)
    fillb_kernel<<<(SEQ * 512 + 255) / 256, 256>>>(out, b_out, SEQ * 512);
    gemm_kernel<<<dim3(8, 3, 4), 128>>>(zb, 512, 0, 0, W_out, 512, 1, 0, 0,
                                        out, 512, 0, 0, 0, 512, 1, 4, 1);
}